// round 7
// baseline (speedup 1.0000x reference)
#include <cuda_runtime.h>
#include <cstdint>

// yoloLoss: preds (B,14,14,30) f32, truths (B,14,14,30) f32 -> scalar f32.
// Warp-autonomous 2-stage cp.async pipelines: every warp owns a private
// double-buffered smem ring and syncs only at warp scope (cp.async groups are
// per-thread). 7 CTAs/SM x 2 warps = 14 independent pipelines per SM, no
// __syncthreads in the hot loop. 896 CTAs -> 1792 pipelines x 14 tiles exact.

#define BOXN    2
#define LABELN  20
#define ALL_BOX 10
#define CVALS   30
#define BATCH_INV (1.0f / 4096.0f)

#define WTILE      32                       // cells per warp-tile
#define WT_FLOATS  (WTILE * CVALS)          // 960 floats per tensor
#define WT_BYTES   (WT_FLOATS * 4)          // 3840 B per tensor
#define WSTAGE_B   (2 * WT_BYTES)           // 7680 B (preds+truths)
#define PCHUNKS    (WT_BYTES / 16)          // 240 16B chunks per tensor
#define NWARPS     2
#define SMEM_BYTES (NWARPS * 2 * WSTAGE_B)  // 30720
#define NBLOCKS    896                      // 1792 warp-pipes, 25088/1792 = 14

__device__ __forceinline__ void cp16(uint32_t dst, const float* src) {
    asm volatile("cp.async.cg.shared.global [%0], [%1], 16;" :: "r"(dst), "l"(src));
}
__device__ __forceinline__ void cp_commit() {
    asm volatile("cp.async.commit_group;");
}
__device__ __forceinline__ void cp_wait1() {
    asm volatile("cp.async.wait_group 1;");
}

__device__ __forceinline__ float cell_loss(const float* __restrict__ P,
                                           const float* __restrict__ T)
{
    const float conf0 = P[4];
    const float conf1 = P[9];
    const float tconf = T[4];

    if (tconf > 0.0f) {
        const float CELLF = 1.0f / 14.0f;
        const float tcx = CELLF * T[0];
        const float tcy = CELLF * T[1];
        const float thw = 0.5f * T[2];
        const float thh = 0.5f * T[3];
        const float t_lt_x = tcx - thw, t_rb_x = tcx + thw;
        const float t_lt_y = tcy - thh, t_rb_y = tcy + thh;
        const float ta = (t_rb_x - t_lt_x) * (t_rb_y - t_lt_y);

        float iou[BOXN];
        #pragma unroll
        for (int b = 0; b < BOXN; b++) {
            const float* pb = P + 5 * b;
            const float pcx = CELLF * pb[0];
            const float pcy = CELLF * pb[1];
            const float phw = 0.5f * pb[2];
            const float phh = 0.5f * pb[3];
            const float p_lt_x = pcx - phw, p_rb_x = pcx + phw;
            const float p_lt_y = pcy - phh, p_rb_y = pcy + phh;
            const float lt_x = fmaxf(p_lt_x, t_lt_x);
            const float lt_y = fmaxf(p_lt_y, t_lt_y);
            const float rb_x = fminf(p_rb_x, t_rb_x);
            const float rb_y = fminf(p_rb_y, t_rb_y);
            const float wx = fmaxf(rb_x - lt_x, 0.0f);
            const float wy = fmaxf(rb_y - lt_y, 0.0f);
            const float inter = wx * wy;
            const float pa = (p_rb_x - p_lt_x) * (p_rb_y - p_lt_y);
            iou[b] = inter / (pa + ta - inter);
        }

        // responsible box: jnp argmax-first-index tie semantics
        int resp;
        if (iou[0] == iou[1]) resp = (conf1 > conf0) ? 1 : 0;
        else                  resp = (iou[1] > iou[0]) ? 1 : 0;
        const float max_iou = fmaxf(iou[0], iou[1]);

        const float* pr = P + 5 * resp;
        const float other_conf = (resp == 0) ? conf1 : conf0;

        const float dx = pr[0] - T[0];
        const float dy = pr[1] - T[1];
        const float dw = sqrtf(pr[2]) - sqrtf(T[2]);
        const float dh = sqrtf(pr[3]) - sqrtf(T[3]);
        float c = 5.0f * (dx * dx + dy * dy + dw * dw + dh * dh);

        const float dc = pr[4] - max_iou;
        c += dc * dc;
        c += 0.5f * other_conf * other_conf;

        #pragma unroll
        for (int k = 0; k < LABELN; k++) {
            const float d = P[ALL_BOX + k] - T[ALL_BOX + k];
            c += d * d;
        }
        return c;
    } else {
        return 0.5f * (conf0 * conf0 + conf1 * conf1);
    }
}

// prefetch one 32-cell warp-tile (preds + truths) into this warp's buffer
__device__ __forceinline__ void prefetch_wtile(int wtile, uint32_t buf,
                                               const float* __restrict__ preds,
                                               const float* __restrict__ truths,
                                               int lane)
{
    const long long base = (long long)wtile * WT_FLOATS;
    const float* gp = preds + base;
    const float* gt = truths + base;
    // 480 16B chunks / 32 lanes = 15 per lane
    #pragma unroll
    for (int k = 0; k < 15; k++) {
        const int idx = k * 32 + lane;           // 0..479
        if (idx < PCHUNKS) cp16(buf + idx * 16, gp + idx * 4);
        else               cp16(buf + idx * 16, gt + (idx - PCHUNKS) * 4);
    }
}

extern __shared__ float smem[];

__global__ void __launch_bounds__(NWARPS * 32)
yolo_loss_kernel(const float* __restrict__ preds,
                 const float* __restrict__ truths,
                 float* __restrict__ out,
                 int n_wtiles, int n_cells, float batch_inv)
{
    const int tid  = threadIdx.x;
    const int wid  = tid >> 5;
    const int lane = tid & 31;

    // this warp's private double buffer
    const uint32_t sbase = (uint32_t)__cvta_generic_to_shared(smem)
                         + (uint32_t)wid * (2 * WSTAGE_B);
    float* const sw = smem + wid * (2 * WSTAGE_B / 4);

    const int pipe   = blockIdx.x * NWARPS + wid;       // warp-pipeline id
    const int stride = gridDim.x * NWARPS;

    float acc = 0.0f;

    if (pipe < n_wtiles)
        prefetch_wtile(pipe, sbase, preds, truths, lane);
    cp_commit();

    int stage = 0;
    for (int t = pipe; t < n_wtiles; t += stride) {
        const int tn = t + stride;
        if (tn < n_wtiles)
            prefetch_wtile(tn, sbase + (stage ^ 1) * WSTAGE_B, preds, truths, lane);
        cp_commit();
        cp_wait1();                 // own groups FIFO -> tile t resident
        __syncwarp();               // cross-lane visibility of staged tile

        const float* P = sw + stage * (WSTAGE_B / 4) + lane * CVALS;
        const float* T = P + WT_FLOATS;
        acc += cell_loss(P, T);

        __syncwarp();               // all lanes done reading before refill
        stage ^= 1;
    }

    // generic remainder (n_cells not multiple of WTILE): pipe 0, direct loads
    if (pipe == 0) {
        const int cell = n_wtiles * WTILE + lane;
        if (cell < n_cells)
            acc += cell_loss(preds + (long long)cell * CVALS,
                             truths + (long long)cell * CVALS);
    }

    // reduce: warp shuffle -> smem -> one atomic per CTA
    #pragma unroll
    for (int off = 16; off > 0; off >>= 1)
        acc += __shfl_down_sync(0xFFFFFFFFu, acc, off);

    __shared__ float warp_sums[NWARPS];
    if (lane == 0) warp_sums[wid] = acc;
    __syncthreads();

    if (tid == 0) {
        float s = 0.0f;
        #pragma unroll
        for (int w = 0; w < NWARPS; w++) s += warp_sums[w];
        atomicAdd(out, s * batch_inv);
    }
}

extern "C" void kernel_launch(void* const* d_in, const int* in_sizes, int n_in,
                              void* d_out, int out_size)
{
    const float* preds  = (const float*)d_in[0];
    const float* truths = (const float*)d_in[1];
    float* out = (float*)d_out;

    const int n_cells  = in_sizes[0] / CVALS;    // 802816
    const int n_wtiles = n_cells / WTILE;        // 25088

    cudaFuncSetAttribute(yolo_loss_kernel,
                         cudaFuncAttributeMaxDynamicSharedMemorySize, SMEM_BYTES);

    cudaMemsetAsync(d_out, 0, sizeof(float), 0);
    yolo_loss_kernel<<<NBLOCKS, NWARPS * 32, SMEM_BYTES, 0>>>(preds, truths, out,
                                                              n_wtiles, n_cells,
                                                              BATCH_INV);
}

// round 8
// speedup vs baseline: 1.0382x; 1.0382x over previous
#include <cuda_runtime.h>
#include <cstdint>

// yoloLoss: preds (B,14,14,30) f32, truths (B,14,14,30) f32 -> scalar f32.
// Bulk-TMA (cp.async.bulk + mbarrier) 3-stage producer/consumer pipeline,
// dynamic ticket scheduling, last-block finalize (no memset node, no atomics
// on out). 2 CTAs/SM x 128 threads; tiles of 128 cells (2x15360B per tile).

#define BOXN    2
#define LABELN  20
#define ALL_BOX 10
#define CVALS   30
#define BATCH_INV (1.0f / 4096.0f)

#define TILE         128
#define TFLOATS      (TILE * CVALS)        // 3840 floats per tensor
#define TBYTES       (TFLOATS * 4)         // 15360 B per tensor
#define STAGE_FLOATS (2 * TFLOATS)         // 7680
#define STAGE_BYTES  (2 * TBYTES)          // 30720
#define NSTAGES      3
#define DATA_BYTES   (NSTAGES * STAGE_BYTES)   // 92160
#define NTHREADS     128
#define GRID_CTAS    296                   // 2 per SM exactly

__device__ unsigned int g_ticket;          // static-init 0
__device__ unsigned int g_done;            // static-init 0
__device__ float        g_partials[GRID_CTAS];

__device__ __forceinline__ uint32_t smem_u32(const void* p) {
    uint32_t a;
    asm("{ .reg .u64 t; cvta.to.shared.u64 t, %1; cvt.u32.u64 %0, t; }"
        : "=r"(a) : "l"(p));
    return a;
}
__device__ __forceinline__ void mbar_init(uint32_t mb, uint32_t cnt) {
    asm volatile("mbarrier.init.shared.b64 [%0], %1;" :: "r"(mb), "r"(cnt) : "memory");
}
__device__ __forceinline__ void mbar_expect_tx(uint32_t mb, uint32_t tx) {
    asm volatile("mbarrier.arrive.expect_tx.shared.b64 _, [%0], %1;"
                 :: "r"(mb), "r"(tx) : "memory");
}
__device__ __forceinline__ void mbar_wait(uint32_t mb, uint32_t parity) {
    asm volatile(
        "{\n\t"
        ".reg .pred P;\n\t"
        "WL_%=:\n\t"
        "mbarrier.try_wait.parity.acquire.cta.shared::cta.b64 P, [%0], %1, 0x989680;\n\t"
        "@P bra.uni WD_%=;\n\t"
        "bra.uni WL_%=;\n\t"
        "WD_%=:\n\t"
        "}"
        :: "r"(mb), "r"(parity) : "memory");
}
__device__ __forceinline__ void bulk_g2s(uint32_t dst, const void* src,
                                         uint32_t bytes, uint32_t mb) {
    asm volatile(
        "cp.async.bulk.shared::cluster.global.mbarrier::complete_tx::bytes "
        "[%0], [%1], %2, [%3];"
        :: "r"(dst), "l"(src), "r"(bytes), "r"(mb) : "memory");
}

__device__ __forceinline__ float cell_loss(const float* __restrict__ P,
                                           const float* __restrict__ T)
{
    const float conf0 = P[4];
    const float conf1 = P[9];
    const float tconf = T[4];

    if (tconf > 0.0f) {
        const float CELLF = 1.0f / 14.0f;
        const float tcx = CELLF * T[0];
        const float tcy = CELLF * T[1];
        const float thw = 0.5f * T[2];
        const float thh = 0.5f * T[3];
        const float t_lt_x = tcx - thw, t_rb_x = tcx + thw;
        const float t_lt_y = tcy - thh, t_rb_y = tcy + thh;
        const float ta = (t_rb_x - t_lt_x) * (t_rb_y - t_lt_y);

        float iou[BOXN];
        #pragma unroll
        for (int b = 0; b < BOXN; b++) {
            const float* pb = P + 5 * b;
            const float pcx = CELLF * pb[0];
            const float pcy = CELLF * pb[1];
            const float phw = 0.5f * pb[2];
            const float phh = 0.5f * pb[3];
            const float p_lt_x = pcx - phw, p_rb_x = pcx + phw;
            const float p_lt_y = pcy - phh, p_rb_y = pcy + phh;
            const float lt_x = fmaxf(p_lt_x, t_lt_x);
            const float lt_y = fmaxf(p_lt_y, t_lt_y);
            const float rb_x = fminf(p_rb_x, t_rb_x);
            const float rb_y = fminf(p_rb_y, t_rb_y);
            const float wx = fmaxf(rb_x - lt_x, 0.0f);
            const float wy = fmaxf(rb_y - lt_y, 0.0f);
            const float inter = wx * wy;
            const float pa = (p_rb_x - p_lt_x) * (p_rb_y - p_lt_y);
            iou[b] = inter / (pa + ta - inter);
        }

        // responsible box: jnp argmax-first-index tie semantics
        int resp;
        if (iou[0] == iou[1]) resp = (conf1 > conf0) ? 1 : 0;
        else                  resp = (iou[1] > iou[0]) ? 1 : 0;
        const float max_iou = fmaxf(iou[0], iou[1]);

        const float* pr = P + 5 * resp;
        const float other_conf = (resp == 0) ? conf1 : conf0;

        const float dx = pr[0] - T[0];
        const float dy = pr[1] - T[1];
        const float dw = sqrtf(pr[2]) - sqrtf(T[2]);
        const float dh = sqrtf(pr[3]) - sqrtf(T[3]);
        float c = 5.0f * (dx * dx + dy * dy + dw * dw + dh * dh);

        const float dc = pr[4] - max_iou;
        c += dc * dc;
        c += 0.5f * other_conf * other_conf;

        #pragma unroll
        for (int k = 0; k < LABELN; k++) {
            const float d = P[ALL_BOX + k] - T[ALL_BOX + k];
            c += d * d;
        }
        return c;
    } else {
        return 0.5f * (conf0 * conf0 + conf1 * conf1);
    }
}

extern __shared__ float sdata[];

__global__ void __launch_bounds__(NTHREADS)
yolo_loss_kernel(const float* __restrict__ preds,
                 const float* __restrict__ truths,
                 float* __restrict__ out,
                 int n_tiles, int n_cells, float batch_inv)
{
    __shared__ __align__(8) uint64_t mbar[NSTAGES];
    __shared__ int   s_tile[NSTAGES];
    __shared__ float warp_sums[NTHREADS / 32];
    __shared__ int   s_last;

    const int tid = threadIdx.x;
    const uint32_t dbase = smem_u32(sdata);

    if (tid == 0) {
        #pragma unroll
        for (int i = 0; i < NSTAGES; i++) mbar_init(smem_u32(&mbar[i]), 1);
    }
    __syncthreads();

    // producer step: fetch a ticket, issue bulk copies into `stage`
    auto prefetch = [&](int stage) {
        if (tid == 0) {
            const int t = (int)atomicAdd(&g_ticket, 1u);
            const uint32_t mb = smem_u32(&mbar[stage]);
            if (t < n_tiles) {
                s_tile[stage] = t;                       // release via arrive below
                mbar_expect_tx(mb, STAGE_BYTES);
                const uint32_t d = dbase + stage * STAGE_BYTES;
                bulk_g2s(d,          preds  + (size_t)t * TFLOATS, TBYTES, mb);
                bulk_g2s(d + TBYTES, truths + (size_t)t * TFLOATS, TBYTES, mb);
            } else {
                s_tile[stage] = -1;
                mbar_expect_tx(mb, 0);                   // completes immediately
            }
        }
    };

    #pragma unroll
    for (int i = 0; i < NSTAGES; i++) prefetch(i);

    float acc = 0.0f;
    int stage = 0, ph = 0;
    for (;;) {
        mbar_wait(smem_u32(&mbar[stage]), ph);
        const int t = s_tile[stage];
        if (t < 0) break;

        const float* P = sdata + stage * STAGE_FLOATS + tid * CVALS;
        const float* T = P + TFLOATS;
        acc += cell_loss(P, T);

        __syncthreads();                 // all lanes done reading this stage
        prefetch(stage);                 // refill with next ticket
        if (++stage == NSTAGES) { stage = 0; ph ^= 1; }
    }

    // generic remainder (n_cells not a multiple of TILE): CTA 0, direct loads
    if (blockIdx.x == 0) {
        const int cell = n_tiles * TILE + tid;
        if (cell < n_cells)
            acc += cell_loss(preds + (long long)cell * CVALS,
                             truths + (long long)cell * CVALS);
    }

    // block reduce -> per-CTA partial
    #pragma unroll
    for (int off = 16; off > 0; off >>= 1)
        acc += __shfl_down_sync(0xFFFFFFFFu, acc, off);
    if ((tid & 31) == 0) warp_sums[tid >> 5] = acc;
    __syncthreads();

    if (tid == 0) {
        float s = 0.0f;
        #pragma unroll
        for (int w = 0; w < NTHREADS / 32; w++) s += warp_sums[w];
        g_partials[blockIdx.x] = s;
        __threadfence();
        const unsigned v = atomicAdd(&g_done, 1u);
        s_last = (v == gridDim.x - 1) ? 1 : 0;
    }
    __syncthreads();

    // last CTA: final reduce, write out, reset counters for next graph replay
    if (s_last) {
        float tot = 0.0f;
        for (int i = tid; i < GRID_CTAS; i += NTHREADS) tot += g_partials[i];
        #pragma unroll
        for (int off = 16; off > 0; off >>= 1)
            tot += __shfl_down_sync(0xFFFFFFFFu, tot, off);
        if ((tid & 31) == 0) warp_sums[tid >> 5] = tot;
        __syncthreads();
        if (tid == 0) {
            float s = 0.0f;
            #pragma unroll
            for (int w = 0; w < NTHREADS / 32; w++) s += warp_sums[w];
            out[0]   = s * batch_inv;
            g_done   = 0u;
            g_ticket = 0u;
        }
    }
}

extern "C" void kernel_launch(void* const* d_in, const int* in_sizes, int n_in,
                              void* d_out, int out_size)
{
    const float* preds  = (const float*)d_in[0];
    const float* truths = (const float*)d_in[1];
    float* out = (float*)d_out;

    const int n_cells = in_sizes[0] / CVALS;     // 802816
    const int n_tiles = n_cells / TILE;          // 6272

    cudaFuncSetAttribute(yolo_loss_kernel,
                         cudaFuncAttributeMaxDynamicSharedMemorySize, DATA_BYTES);

    yolo_loss_kernel<<<GRID_CTAS, NTHREADS, DATA_BYTES, 0>>>(preds, truths, out,
                                                             n_tiles, n_cells,
                                                             BATCH_INV);
}